// round 1
// baseline (speedup 1.0000x reference)
#include <cuda_runtime.h>

// Per-frequency interpolation table, computed once per launch by coeff_kernel.
// out[b,i,:] = c0[i] * H[b, base[i], :] + c1[i] * H[b, base[i]+1, :]
// (boundary extrapolation h0 / hN folded into (c0,c1,base) so the main
//  kernel is branch-free and purely 2-tap).
#define MAX_NFFT 8192
__device__ float2 g_coeff[MAX_NFFT];
__device__ int    g_base[MAX_NFFT];

__global__ void coeff_kernel(const float* __restrict__ pilot_pos,
                             const float* __restrict__ decay_param,
                             int NP, int Nfft) {
    extern __shared__ float s_loc[];  // extended knots: [0, loc..., Nfft-1], NP+2 entries
    const int tid = threadIdx.x;
    for (int k = tid; k < NP; k += blockDim.x)
        s_loc[k + 1] = pilot_pos[k] - 1.0f;
    if (tid == 0) {
        s_loc[0]      = 0.0f;
        s_loc[NP + 1] = (float)(Nfft - 1);
    }
    __syncthreads();

    // softplus(decay_param[0]) in fp32, numerically safe
    float dp = decay_param[0];
    float decay = (dp > 20.0f) ? dp : log1pf(expf(dp));

    int i = blockIdx.x * blockDim.x + tid;
    if (i >= Nfft) return;
    float fi = (float)i;

    // searchsorted(loc_ext, i, side='right') - 1, clipped to [0, NP]
    int lo = 0, hi = NP + 2;
    while (lo < hi) {
        int mid = (lo + hi) >> 1;
        if (s_loc[mid] <= fi) lo = mid + 1; else hi = mid;
    }
    int left = lo - 1;
    if (left < 0)  left = 0;
    if (left > NP) left = NP;

    float x0 = s_loc[left], x1 = s_loc[left + 1];
    float wl = expf(-decay * fabsf(fi - x0));
    float wr = expf(-decay * fabsf(x1 - fi));
    float w  = wl + wr + 1e-12f;
    float al = wl / w, ar = wr / w;

    float c0, c1;
    int base;
    if (left == 0) {
        // y0 = h0 = (1+t)*H[0] - t*H[1],  t = loc0/(loc1-loc0);  y1 = H[0]
        float l0 = s_loc[1], l1 = s_loc[2];
        float t = l0 / (l1 - l0);
        base = 0;
        c0 = al * (1.0f + t) + ar;
        c1 = -al * t;
    } else if (left == NP) {
        // y0 = H[NP-1];  y1 = hN = (1+u)*H[NP-1] - u*H[NP-2]
        float lN1 = s_loc[NP], lN2 = s_loc[NP - 1];
        float u = ((float)(Nfft - 1) - lN1) / (lN1 - lN2);
        base = NP - 2;
        c0 = -ar * u;
        c1 = al + ar * (1.0f + u);
    } else {
        base = left - 1;
        c0 = al;
        c1 = ar;
    }
    g_coeff[i] = make_float2(c0, c1);
    g_base[i]  = base;
}

// Streaming pass: one thread produces 2 output frequencies (16B float4 store).
__global__ void __launch_bounds__(256)
interp_kernel(const float2* __restrict__ H,   // [B, NP] complex as float2
              float* __restrict__ out,        // [B, Nfft, 2]
              int NP, int pairs) {
    int p = blockIdx.x * blockDim.x + threadIdx.x;
    if (p >= pairs) return;
    int b = blockIdx.y;

    const float2* Hrow = H + (size_t)b * NP;

    float4 c  = *((const float4*)g_coeff + p);  // (c0,c1) for i0, (c0,c1) for i0+1
    int2   bs = *((const int2*)g_base + p);

    float2 y00 = __ldg(Hrow + bs.x);
    float2 y01 = __ldg(Hrow + bs.x + 1);
    float2 y10 = __ldg(Hrow + bs.y);
    float2 y11 = __ldg(Hrow + bs.y + 1);

    float4 r;
    r.x = c.x * y00.x + c.y * y01.x;
    r.y = c.x * y00.y + c.y * y01.y;
    r.z = c.z * y10.x + c.w * y11.x;
    r.w = c.z * y10.y + c.w * y11.y;

    float4* o4 = (float4*)out + (size_t)b * pairs + p;
    __stcs(o4, r);  // streaming store: output is never re-read
}

extern "C" void kernel_launch(void* const* d_in, const int* in_sizes, int n_in,
                              void* d_out, int out_size) {
    const float* LS_ri       = (const float*)d_in[0];  // [B, NP, 2]
    const float* pilot_pos   = (const float*)d_in[1];  // [NP]
    const float* decay_param = (const float*)d_in[2];  // [1]
    // d_in[3] is Nfft on device; recover all shapes host-side instead:
    int NP   = in_sizes[1];
    int B    = in_sizes[0] / (NP * 2);
    int Nfft = out_size / (B * 2);

    // Kernel A: per-frequency coefficient table (tiny).
    {
        int threads = 256;
        int blocks  = (Nfft + threads - 1) / threads;
        size_t smem = (size_t)(NP + 2) * sizeof(float);
        coeff_kernel<<<blocks, threads, smem>>>(pilot_pos, decay_param, NP, Nfft);
    }

    // Kernel B: streaming interpolation.
    {
        int pairs = Nfft / 2;
        dim3 block(256);
        dim3 grid((pairs + block.x - 1) / block.x, B);
        interp_kernel<<<grid, block>>>((const float2*)LS_ri, (float*)d_out, NP, pairs);
    }
}

// round 2
// speedup vs baseline: 1.0355x; 1.0355x over previous
#include <cuda_runtime.h>

// Per-frequency interpolation table, computed once per launch by coeff_kernel.
// out[b,i,:] = c0[i] * H[b, base[i], :] + c1[i] * H[b, base[i]+1, :]
// (boundary extrapolation h0 / hN folded into (c0,c1,base)).
#define MAX_NFFT 8192
#define MAX_NP   4096
__device__ __align__(16) float2 g_coeff[MAX_NFFT];
__device__ __align__(16) int    g_base[MAX_NFFT];

__global__ void coeff_kernel(const float* __restrict__ pilot_pos,
                             const float* __restrict__ decay_param,
                             int NP, int Nfft) {
    extern __shared__ float s_loc[];  // extended knots: [0, loc..., Nfft-1], NP+2 entries
    const int tid = threadIdx.x;
    for (int k = tid; k < NP; k += blockDim.x)
        s_loc[k + 1] = pilot_pos[k] - 1.0f;
    if (tid == 0) {
        s_loc[0]      = 0.0f;
        s_loc[NP + 1] = (float)(Nfft - 1);
    }
    __syncthreads();

    float dp = decay_param[0];
    float decay = (dp > 20.0f) ? dp : log1pf(expf(dp));

    int i = blockIdx.x * blockDim.x + tid;
    if (i >= Nfft) return;
    float fi = (float)i;

    // searchsorted(loc_ext, i, side='right') - 1, clipped to [0, NP]
    int lo = 0, hi = NP + 2;
    while (lo < hi) {
        int mid = (lo + hi) >> 1;
        if (s_loc[mid] <= fi) lo = mid + 1; else hi = mid;
    }
    int left = lo - 1;
    if (left < 0)  left = 0;
    if (left > NP) left = NP;

    float x0 = s_loc[left], x1 = s_loc[left + 1];
    float wl = expf(-decay * fabsf(fi - x0));
    float wr = expf(-decay * fabsf(x1 - fi));
    float w  = wl + wr + 1e-12f;
    float al = wl / w, ar = wr / w;

    float c0, c1;
    int base;
    if (left == 0) {
        // y0 = h0 = (1+t)*H[0] - t*H[1],  t = loc0/(loc1-loc0);  y1 = H[0]
        float l0 = s_loc[1], l1 = s_loc[2];
        float t = l0 / (l1 - l0);
        base = 0;
        c0 = al * (1.0f + t) + ar;
        c1 = -al * t;
    } else if (left == NP) {
        // y0 = H[NP-1];  y1 = hN = (1+u)*H[NP-1] - u*H[NP-2]
        float lN1 = s_loc[NP], lN2 = s_loc[NP - 1];
        float u = ((float)(Nfft - 1) - lN1) / (lN1 - lN2);
        base = NP - 2;
        c0 = -ar * u;
        c1 = al + ar * (1.0f + u);
    } else {
        base = left - 1;
        c0 = al;
        c1 = ar;
    }
    g_coeff[i] = make_float2(c0, c1);
    g_base[i]  = base;
}

// One block per batch row b. Stage H[b,:] in shared memory (LDS gathers,
// no dependent global gather), then stream warp-contiguous float4 outputs.
__global__ void __launch_bounds__(256, 6)
interp_kernel(const float2* __restrict__ H,   // [B, NP] complex as float2
              float* __restrict__ out,        // [B, Nfft, 2]
              int NP, int nf4) {               // nf4 = Nfft/2 (float4 per row)
    extern __shared__ float2 sH[];             // NP float2
    const int tid = threadIdx.x;
    const int b   = blockIdx.x;

    // Stage the H row: coalesced float4 loads when possible.
    const float2* Hrow = H + (size_t)b * NP;
    int np4 = NP >> 1;                         // float4 chunks (NP assumed even here)
    const float4* Hrow4 = (const float4*)Hrow;
    float4* sH4 = (float4*)sH;
    for (int k = tid; k < np4; k += blockDim.x)
        sH4[k] = Hrow4[k];
    if ((NP & 1) && tid == 0) sH[NP - 1] = Hrow[NP - 1];
    __syncthreads();

    const float4* c4 = (const float4*)g_coeff;  // 2 (c0,c1) pairs per float4
    const int2*   b2 = (const int2*)g_base;     // 2 bases per int2
    float4* orow = (float4*)out + (size_t)b * nf4;

    #pragma unroll 4
    for (int f4 = tid; f4 < nf4; f4 += blockDim.x) {
        float4 c  = c4[f4];
        int2   bs = b2[f4];

        float2 y00 = sH[bs.x];
        float2 y01 = sH[bs.x + 1];
        float2 y10 = sH[bs.y];
        float2 y11 = sH[bs.y + 1];

        float4 r;
        r.x = c.x * y00.x + c.y * y01.x;
        r.y = c.x * y00.y + c.y * y01.y;
        r.z = c.z * y10.x + c.w * y11.x;
        r.w = c.z * y10.y + c.w * y11.y;

        __stcs(orow + f4, r);   // streaming store: output never re-read
    }
}

extern "C" void kernel_launch(void* const* d_in, const int* in_sizes, int n_in,
                              void* d_out, int out_size) {
    const float* LS_ri       = (const float*)d_in[0];  // [B, NP, 2]
    const float* pilot_pos   = (const float*)d_in[1];  // [NP]
    const float* decay_param = (const float*)d_in[2];  // [1]
    int NP   = in_sizes[1];
    int B    = in_sizes[0] / (NP * 2);
    int Nfft = out_size / (B * 2);

    // Kernel A: per-frequency coefficient table (tiny).
    {
        int threads = 256;
        int blocks  = (Nfft + threads - 1) / threads;
        size_t smem = (size_t)(NP + 2) * sizeof(float);
        coeff_kernel<<<blocks, threads, smem>>>(pilot_pos, decay_param, NP, Nfft);
    }

    // Kernel B: one block per batch row, H row staged in smem.
    {
        int nf4 = Nfft / 2;
        dim3 block(256);
        dim3 grid(B);
        size_t smem = (size_t)NP * sizeof(float2);
        interp_kernel<<<grid, block, smem>>>((const float2*)LS_ri, (float*)d_out,
                                             NP, nf4);
    }
}